// round 15
// baseline (speedup 1.0000x reference)
#include <cuda_runtime.h>
#include <cuda_bf16.h>
#include <cstdint>

#define BB 4
#define CC 512
#define HH 128
#define WW 128
#define NN (HH*WW)      // 16384
#define KCODE 32
#define EPSF 1e-5f

// ---------------- device scratch ----------------
__device__ float g_x2[BB*NN];                               // sum_c z^2 per pixel
__device__ float g_asum[BB*KCODE];
__device__ float g_aggT[BB*CC*KCODE];                       // agg transposed [b][c][k]
__device__ float g_feat[BB*CC];
__device__ float g_gamma[BB*CC];
__device__ float g_c2[KCODE];
__device__ __align__(256) __nv_bfloat16 g_whi[CC*CC];       // conv_w split [o][c]
__device__ __align__(256) __nv_bfloat16 g_wlo[CC*CC];
__device__ __align__(256) __nv_bfloat16 g_cwhi[KCODE*CC];   // codewords split [k][c]
__device__ __align__(256) __nv_bfloat16 g_cwlo[KCODE*CC];
__device__ __align__(256) __nv_bfloat16 g_xthi[(size_t)BB*NN*CC]; // x transposed+split [b][n][c]
__device__ __align__(256) __nv_bfloat16 g_xtlo[(size_t)BB*NN*CC];
__device__ __align__(256) __nv_bfloat16 g_znhi[(size_t)BB*NN*CC]; // z split [b][n][c]
__device__ __align__(256) __nv_bfloat16 g_znlo[(size_t)BB*NN*CC];

// ---------------- helpers ----------------
__device__ __forceinline__ uint32_t smem_u32(const void* p) {
    uint32_t a;
    asm("{ .reg .u64 t; cvta.to.shared.u64 t, %1; cvt.u32.u64 %0, t; }" : "=r"(a) : "l"(p));
    return a;
}
#define SW128(off) ((off) ^ (((off) >> 3) & 0x70))
#define CP16(dst, src) asm volatile("cp.async.cg.shared.global [%0], [%1], 16;" \
    :: "r"(dst), "l"(__cvta_generic_to_global(src)) : "memory")
#define CP_COMMIT() asm volatile("cp.async.commit_group;" ::: "memory")
#define CP_WAIT0()  asm volatile("cp.async.wait_group 0;" ::: "memory")
#define CP_WAIT1()  asm volatile("cp.async.wait_group 1;" ::: "memory")

__device__ __forceinline__ void ldsm4(uint32_t addr, uint32_t* r) {
    asm volatile("ldmatrix.sync.aligned.m8n8.x4.shared.b16 {%0,%1,%2,%3}, [%4];"
        : "=r"(r[0]), "=r"(r[1]), "=r"(r[2]), "=r"(r[3]) : "r"(addr));
}
__device__ __forceinline__ void ldsm4t(uint32_t addr, uint32_t* r) {
    asm volatile("ldmatrix.sync.aligned.m8n8.x4.trans.shared.b16 {%0,%1,%2,%3}, [%4];"
        : "=r"(r[0]), "=r"(r[1]), "=r"(r[2]), "=r"(r[3]) : "r"(addr));
}
__device__ __forceinline__ void mma16816(float* c, const uint32_t* a, const uint32_t* b) {
    asm volatile("mma.sync.aligned.m16n8k16.row.col.f32.bf16.bf16.f32 "
        "{%0,%1,%2,%3}, {%4,%5,%6,%7}, {%8,%9}, {%0,%1,%2,%3};"
        : "+f"(c[0]), "+f"(c[1]), "+f"(c[2]), "+f"(c[3])
        : "r"(a[0]), "r"(a[1]), "r"(a[2]), "r"(a[3]), "r"(b[0]), "r"(b[1]));
}

// ---------------- kc_w: split conv_w + codewords + c2 + zero accumulators ----------------
__global__ void kc_w(const float* __restrict__ w, const float* __restrict__ cw) {
    if (blockIdx.x >= 1024) {
        __shared__ float red[256];
        int k = blockIdx.x - 1024, t = threadIdx.x;
        float s = 0.f;
        for (int i = t; i < CC; i += 256) {
            float v = cw[k*CC + i];
            __nv_bfloat16 hi = __float2bfloat16(v);
            __nv_bfloat16 lo = __float2bfloat16(v - __bfloat162float(hi));
            g_cwhi[k*CC + i] = hi; g_cwlo[k*CC + i] = lo;
            s = fmaf(v, v, s);
        }
        red[t] = s;
        __syncthreads();
        for (int st = 128; st > 0; st >>= 1) {
            if (t < st) red[t] += red[t + st];
            __syncthreads();
        }
        if (t == 0) g_c2[k] = red[0];
        return;
    }
    int i = blockIdx.x * blockDim.x + threadIdx.x;
    int stride = 1024 * blockDim.x;
    if (i < CC*CC) {
        float v = w[i];
        __nv_bfloat16 hi = __float2bfloat16(v);
        __nv_bfloat16 lo = __float2bfloat16(v - __bfloat162float(hi));
        g_whi[i] = hi; g_wlo[i] = lo;
    }
    for (int j = i; j < BB*CC*KCODE; j += stride) g_aggT[j] = 0.f;
    for (int j = i; j < BB*NN; j += stride) g_x2[j] = 0.f;
    if (i < BB*KCODE) g_asum[i] = 0.f;
}

// ---------------- kc_x: transpose + split x -> [b][n][c] bf16 hi/lo ----------------
__global__ __launch_bounds__(256) void kc_x(const float* __restrict__ x) {
    __shared__ float tile[64][33];
    int b = blockIdx.z;
    int c0 = blockIdx.y * 64;
    int n0 = blockIdx.x * 32;
    int t = threadIdx.x;
    const float* xb = x + (size_t)b * CC * NN;

    int nn = t & 31, cg = t >> 5;
    #pragma unroll
    for (int i = 0; i < 8; i++) {
        int cc = cg * 8 + i;
        tile[cc][nn] = xb[(size_t)(c0 + cc) * NN + n0 + nn];
    }
    __syncthreads();
    int pc = t & 31, nr = t >> 5;
    #pragma unroll
    for (int i = 0; i < 4; i++) {
        int n = nr + 8 * i;
        float v0 = tile[pc * 2][n], v1 = tile[pc * 2 + 1][n];
        __nv_bfloat16 h0 = __float2bfloat16(v0), h1 = __float2bfloat16(v1);
        __nv_bfloat16 l0 = __float2bfloat16(v0 - __bfloat162float(h0));
        __nv_bfloat16 l1 = __float2bfloat16(v1 - __bfloat162float(h1));
        size_t idx = ((size_t)b * NN + n0 + n) * (CC/2) + (c0/2) + pc;
        reinterpret_cast<__nv_bfloat162*>(g_xthi)[idx] = __nv_bfloat162(h0, h1);
        reinterpret_cast<__nv_bfloat162*>(g_xtlo)[idx] = __nv_bfloat162(l0, l1);
    }
}

// ---------------- k1_mma: conv GEMM (split bf16) + BN2 + ReLU ----------------
// Block 64(M=o) x 256(N=n), BK=64, 8 warps in 2(m) x 4(n), warp tile 32x64.
// acc = 64 regs/thread -> headroom below the 255 cap for fragment prefetch.
// Stage: A_hi 8K | A_lo 8K | B_hi 32K | B_lo 32K = 80KB, 2 stages = 160KB.
static constexpr int K1_STAGE = 81920;
static constexpr int SM_K1 = 2 * K1_STAGE;        // 160KB

__global__ __launch_bounds__(256, 1)
void k1_mma(const float* __restrict__ bg, const float* __restrict__ bb_,
            const float* __restrict__ bm, const float* __restrict__ bv)
{
    extern __shared__ char sm[];
    uint32_t sbase = smem_u32(sm);

    int tid = threadIdx.x;
    int lane = tid & 31, wid = tid >> 5;
    int wm = wid & 1, wn = wid >> 1;             // warp tile: rows wm*32, cols wn*64
    int m0 = blockIdx.x * 64;
    int n0 = blockIdx.y * 256;
    int b  = blockIdx.z;

    auto load_stage = [&](int ch, int st) {
        uint32_t s0 = sbase + st * K1_STAGE;
        #pragma unroll
        for (int i = 0; i < 2; i++) {           // A: 64 rows x 8 chunks16
            int idx = tid + 256 * i;
            int row = idx >> 3, cc8 = idx & 7;
            uint32_t dst = s0 + SW128((uint32_t)(row * 128 + cc8 * 16));
            size_t aoff = (size_t)(m0 + row) * CC + ch * 64 + cc8 * 8;
            CP16(dst,         g_whi + aoff);
            CP16(dst + 8192,  g_wlo + aoff);
        }
        #pragma unroll
        for (int i = 0; i < 8; i++) {           // B: 256 rows x 8 chunks16
            int idx = tid + 256 * i;
            int row = idx >> 3, cc8 = idx & 7;
            uint32_t dst = s0 + 16384 + SW128((uint32_t)(row * 128 + cc8 * 16));
            size_t boff = ((size_t)b * NN + n0 + row) * CC + ch * 64 + cc8 * 8;
            CP16(dst,          g_xthi + boff);
            CP16(dst + 32768,  g_xtlo + boff);
        }
    };

    float acc[2][8][4];
    #pragma unroll
    for (int mi = 0; mi < 2; mi++)
        #pragma unroll
        for (int nj = 0; nj < 8; nj++)
            #pragma unroll
            for (int r = 0; r < 4; r++) acc[mi][nj][r] = 0.f;

    int rowA = lane & 15, chA = lane >> 4;
    int rowB = ((lane >> 4) << 3) + (lane & 7), chB = (lane >> 3) & 1;

    load_stage(0, 0); CP_COMMIT();

    for (int ch = 0; ch < 8; ch++) {
        CP_WAIT0();
        __syncthreads();
        if (ch < 7) { load_stage(ch + 1, (ch + 1) & 1); CP_COMMIT(); }

        uint32_t s0 = sbase + (ch & 1) * K1_STAGE;
        #pragma unroll
        for (int ks = 0; ks < 4; ks++) {
            uint32_t ahi[2][4], alo[2][4], bhi[4][4], blo[4][4];
            #pragma unroll
            for (int mi = 0; mi < 2; mi++) {
                uint32_t off = SW128((uint32_t)((wm*32 + mi*16 + rowA) * 128 + ks*32 + chA*16));
                ldsm4(s0 + off, ahi[mi]);
                ldsm4(s0 + 8192 + off, alo[mi]);
            }
            #pragma unroll
            for (int np = 0; np < 4; np++) {
                uint32_t off = 16384 + SW128((uint32_t)((wn*64 + np*16 + rowB) * 128 + ks*32 + chB*16));
                ldsm4(s0 + off, bhi[np]);
                ldsm4(s0 + 32768 + off, blo[np]);
            }
            #pragma unroll
            for (int mi = 0; mi < 2; mi++)
                #pragma unroll
                for (int nj = 0; nj < 8; nj++) {
                    const uint32_t* bh = &bhi[nj >> 1][(nj & 1) * 2];
                    const uint32_t* bl = &blo[nj >> 1][(nj & 1) * 2];
                    mma16816(acc[mi][nj], ahi[mi], bh);
                    mma16816(acc[mi][nj], ahi[mi], bl);
                    mma16816(acc[mi][nj], alo[mi], bh);
                }
        }
    }
    __syncthreads();

    // ---- Epilogue: BN2+ReLU; stage split bf16 [n 256][o 64 (+8 pad)]; x2 ----
    __nv_bfloat16* sh_hi = reinterpret_cast<__nv_bfloat16*>(sm);
    __nv_bfloat16* sh_lo = sh_hi + 256 * 72;

    float v2acc[16];
    #pragma unroll
    for (int j = 0; j < 16; j++) v2acc[j] = 0.f;

    #pragma unroll
    for (int mi = 0; mi < 2; mi++) {
        #pragma unroll
        for (int rr = 0; rr < 2; rr++) {
            int o_loc = wm*32 + mi*16 + rr*8 + (lane >> 2);
            int o = m0 + o_loc;
            float sc = bg[o] * rsqrtf(bv[o] + EPSF);
            float sh2 = bb_[o] - bm[o] * sc;
            #pragma unroll
            for (int nj = 0; nj < 8; nj++) {
                float z0 = fmaxf(fmaf(acc[mi][nj][rr*2 + 0], sc, sh2), 0.f);
                float z1 = fmaxf(fmaf(acc[mi][nj][rr*2 + 1], sc, sh2), 0.f);
                v2acc[nj*2 + 0] += z0 * z0;
                v2acc[nj*2 + 1] += z1 * z1;
                __nv_bfloat16 h0 = __float2bfloat16(z0), h1 = __float2bfloat16(z1);
                __nv_bfloat16 l0 = __float2bfloat16(z0 - __bfloat162float(h0));
                __nv_bfloat16 l1 = __float2bfloat16(z1 - __bfloat162float(h1));
                int n_loc = wn*64 + nj*8 + (lane & 3) * 2;
                sh_hi[(n_loc + 0) * 72 + o_loc] = h0;
                sh_hi[(n_loc + 1) * 72 + o_loc] = h1;
                sh_lo[(n_loc + 0) * 72 + o_loc] = l0;
                sh_lo[(n_loc + 1) * 72 + o_loc] = l1;
            }
        }
    }
    #pragma unroll
    for (int j = 0; j < 16; j++) {
        v2acc[j] += __shfl_xor_sync(0xffffffffu, v2acc[j], 4);
        v2acc[j] += __shfl_xor_sync(0xffffffffu, v2acc[j], 8);
        v2acc[j] += __shfl_xor_sync(0xffffffffu, v2acc[j], 16);
    }
    if ((lane >> 2) == 0) {
        // only the half of the block with wm==0 contributes the reduced sums for
        // rows 0-31; wm==1 warps hold rows 32-63 of the same n columns -> both add.
        #pragma unroll
        for (int j = 0; j < 16; j++) {
            int n_loc = wn*64 + (j >> 1) * 8 + (lane & 3) * 2 + (j & 1);
            atomicAdd(&g_x2[b*NN + n0 + n_loc], v2acc[j]);
        }
    }
    __syncthreads();
    #pragma unroll
    for (int i = 0; i < 8; i++) {
        int idx = tid + 256 * i;
        int row = idx >> 3, c16 = idx & 7;
        uint4 vh = *reinterpret_cast<const uint4*>(sh_hi + row * 72 + c16 * 8);
        uint4 vl = *reinterpret_cast<const uint4*>(sh_lo + row * 72 + c16 * 8);
        size_t di = ((size_t)b*NN + n0 + row) * CC + m0 + c16 * 8;
        *reinterpret_cast<uint4*>(&g_znhi[di]) = vh;
        *reinterpret_cast<uint4*>(&g_znlo[di]) = vl;
    }
}

// ---------------- k23_mma: fused assignment + aggregation ----------------
static constexpr int K2_CW_HI = 0;          // phase1 cw; phase2 z-stage buf 0
static constexpr int K2_CW_LO = 32768;
static constexpr int K2_ZST   = 65536;      // phase1 z double buffer (2 x 64KB)
static constexpr int K2_X2S   = 196608;     // 1KB
static constexpr int K2_ASUM  = 197632;     // 128B
static constexpr int K2_ASG   = 197760;     // assign hi 16KB | lo 16KB
static constexpr int SM_K23   = 230528;

__global__ __launch_bounds__(256, 1)
void k23_mma(const float* __restrict__ scale)
{
    extern __shared__ char sm[];
    uint32_t sbase = smem_u32(sm);
    int tid = threadIdx.x, lane = tid & 31, w = tid >> 5;
    int b = blockIdx.y;
    int n0 = blockIdx.x * 256;
    int q = lane >> 2;

    if (tid < 32) *reinterpret_cast<float*>(sm + K2_ASUM + tid*4) = 0.f;
    const uint4* cwh4 = reinterpret_cast<const uint4*>(g_cwhi);
    const uint4* cwl4 = reinterpret_cast<const uint4*>(g_cwlo);
    #pragma unroll
    for (int i = 0; i < 8; i++) {
        int idx = tid + 256 * i;
        int row = idx >> 6, cb = idx & 63;
        uint32_t off = (uint32_t)(row * 1024 + ((cb * 16) ^ ((row & 7) << 4)));
        *reinterpret_cast<uint4*>(sm + K2_CW_HI + off) = cwh4[row * 64 + cb];
        *reinterpret_cast<uint4*>(sm + K2_CW_LO + off) = cwl4[row * 64 + cb];
    }
    *reinterpret_cast<float*>(sm + K2_X2S + tid*4) = g_x2[b*NN + n0 + tid];

    auto load_z = [&](int ch, uint32_t base) {
        uint32_t s0 = sbase + base;
        #pragma unroll
        for (int i = 0; i < 8; i++) {
            int idx = tid + 256 * i;
            int row = idx >> 3, col = idx & 7;
            uint32_t dst = s0 + SW128((uint32_t)(row * 128 + col * 16));
            size_t src = ((size_t)b*NN + n0 + row) * CC + ch * 64 + col * 8;
            CP16(dst,         g_znhi + src);
            CP16(dst + 32768, g_znlo + src);
        }
    };
    auto load_z2 = [&](int ch, uint32_t base) {
        uint32_t s0 = sbase + base;
        #pragma unroll
        for (int i = 0; i < 8; i++) {
            int idx = tid + 256 * i;
            int row = idx >> 6, cb = idx & 63;
            uint32_t byte = (uint32_t)(row * 1024 + cb * 16);
            uint32_t sw = byte ^ (((uint32_t)row & 7) << 4);
            size_t src = ((size_t)b*NN + n0 + ch*32 + row) * CC + cb * 8;
            CP16(s0 + sw,         g_znhi + src);
            CP16(s0 + 32768 + sw, g_znlo + src);
        }
    };

    float acc[2][4][4];
    #pragma unroll
    for (int mf = 0; mf < 2; mf++)
        #pragma unroll
        for (int nj = 0; nj < 4; nj++)
            #pragma unroll
            for (int r = 0; r < 4; r++) acc[mf][nj][r] = 0.f;

    load_z(0, K2_ZST);
    CP_COMMIT();

    // ---- Phase 1: xc GEMM ----
    for (int ch = 0; ch < 8; ch++) {
        CP_WAIT0();
        __syncthreads();
        if (ch < 7) { load_z(ch + 1, K2_ZST + ((ch + 1) & 1) * 65536); CP_COMMIT(); }
        uint32_t zs = sbase + K2_ZST + (ch & 1) * 65536;
        #pragma unroll
        for (int ks = 0; ks < 4; ks++) {
            uint32_t ah[2][4], al[2][4], bh[2][4], bl[2][4];
            #pragma unroll
            for (int mf = 0; mf < 2; mf++) {
                int code = mf * 16 + (lane & 15);
                uint32_t off = (uint32_t)(code * 1024 +
                    ((ch*128 + ks*32 + (lane >> 4) * 16) ^ ((code & 7) << 4)));
                ldsm4(sbase + K2_CW_HI + off, ah[mf]);
                ldsm4(sbase + K2_CW_LO + off, al[mf]);
            }
            #pragma unroll
            for (int p = 0; p < 2; p++) {
                int row = w*32 + p*16 + ((lane >> 4) << 3) + (lane & 7);
                uint32_t off = SW128((uint32_t)(row * 128 + ks*32 + ((lane >> 3) & 1) * 16));
                ldsm4(zs + off, bh[p]);
                ldsm4(zs + off + 32768, bl[p]);
            }
            #pragma unroll
            for (int mf = 0; mf < 2; mf++)
                #pragma unroll
                for (int nj = 0; nj < 4; nj++) {
                    const uint32_t* Bh = &bh[nj >> 1][(nj & 1) * 2];
                    const uint32_t* Bl = &bl[nj >> 1][(nj & 1) * 2];
                    mma16816(acc[mf][nj], ah[mf], Bh);
                    mma16816(acc[mf][nj], ah[mf], Bl);
                    mma16816(acc[mf][nj], al[mf], Bh);
                }
        }
    }

    __syncthreads();
    load_z2(0, 0);     CP_COMMIT();
    load_z2(1, 65536); CP_COMMIT();

    // ---- softmax over codes (m axis) ----
    float s4[4], c24[4];
    #pragma unroll
    for (int ci = 0; ci < 4; ci++) {
        s4[ci] = __ldg(&scale[q + 8*ci]);
        c24[ci] = g_c2[q + 8*ci];
    }
    float l[4][8];
    #pragma unroll
    for (int mf = 0; mf < 2; mf++)
        #pragma unroll
        for (int nj = 0; nj < 4; nj++)
            #pragma unroll
            for (int r = 0; r < 4; r++) {
                int ci = mf*2 + (r >> 1);
                int j  = nj*2 + (r & 1);
                int col = nj*8 + (lane & 3)*2 + (r & 1);
                float x2v = *reinterpret_cast<const float*>(sm + K2_X2S + (w*32 + col)*4);
                l[ci][j] = s4[ci] * (x2v - 2.f * acc[mf][nj][r] + c24[ci]);
            }
    float mx[8], sme[8], inv[8];
    #pragma unroll
    for (int j = 0; j < 8; j++) {
        mx[j] = fmaxf(fmaxf(l[0][j], l[1][j]), fmaxf(l[2][j], l[3][j]));
        mx[j] = fmaxf(mx[j], __shfl_xor_sync(0xffffffffu, mx[j], 4));
        mx[j] = fmaxf(mx[j], __shfl_xor_sync(0xffffffffu, mx[j], 8));
        mx[j] = fmaxf(mx[j], __shfl_xor_sync(0xffffffffu, mx[j], 16));
    }
    #pragma unroll
    for (int j = 0; j < 8; j++) {
        sme[j] = 0.f;
        #pragma unroll
        for (int ci = 0; ci < 4; ci++) {
            float e = __expf(l[ci][j] - mx[j]);
            l[ci][j] = e; sme[j] += e;
        }
        sme[j] += __shfl_xor_sync(0xffffffffu, sme[j], 4);
        sme[j] += __shfl_xor_sync(0xffffffffu, sme[j], 8);
        sme[j] += __shfl_xor_sync(0xffffffffu, sme[j], 16);
        inv[j] = 1.f / sme[j];
    }
    float apart[4];
    #pragma unroll
    for (int ci = 0; ci < 4; ci++) apart[ci] = 0.f;
    #pragma unroll
    for (int ci = 0; ci < 4; ci++)
        #pragma unroll
        for (int j = 0; j < 8; j++) {
            float av = l[ci][j] * inv[j];
            apart[ci] += av;
            int code = q + 8*ci;
            int pix = w*32 + (j >> 1)*8 + (lane & 3)*2 + (j & 1);
            __nv_bfloat16 hv = __float2bfloat16(av);
            __nv_bfloat16 lv = __float2bfloat16(av - __bfloat162float(hv));
            uint32_t aoff = (uint32_t)(code*512) +
                ((((uint32_t)pix >> 3) ^ (uint32_t)(code & 7)) << 4) + ((uint32_t)pix & 7) * 2;
            *reinterpret_cast<__nv_bfloat16*>(sm + K2_ASG + aoff) = hv;
            *reinterpret_cast<__nv_bfloat16*>(sm + K2_ASG + 16384 + aoff) = lv;
        }
    #pragma unroll
    for (int ci = 0; ci < 4; ci++) {
        apart[ci] += __shfl_xor_sync(0xffffffffu, apart[ci], 1);
        apart[ci] += __shfl_xor_sync(0xffffffffu, apart[ci], 2);
    }
    if ((lane & 3) == 0) {
        #pragma unroll
        for (int ci = 0; ci < 4; ci++)
            atomicAdd(reinterpret_cast<float*>(sm + K2_ASUM + (q + 8*ci)*4), apart[ci]);
    }
    __syncthreads();
    if (tid < 32)
        atomicAdd(&g_asum[b*KCODE + tid], *reinterpret_cast<float*>(sm + K2_ASUM + tid*4));

    // ---- Phase 2: C[m=codes 32][n=c 64/warp], contraction over 256 pixels ----
    float acc2[2][8][4];
    #pragma unroll
    for (int mf = 0; mf < 2; mf++)
        #pragma unroll
        for (int nj = 0; nj < 8; nj++)
            #pragma unroll
            for (int r = 0; r < 4; r++) acc2[mf][nj][r] = 0.f;

    for (int ch2 = 0; ch2 < 8; ch2++) {
        if (ch2 == 7) { CP_WAIT0(); } else { CP_WAIT1(); }
        __syncthreads();
        if (ch2 < 6) { load_z2(ch2 + 2, ((ch2 + 2) % 3) * 65536); CP_COMMIT(); }
        uint32_t s0 = sbase + (ch2 % 3) * 65536;

        #pragma unroll
        for (int ks = 0; ks < 2; ks++) {
            uint32_t Ah[2][4], Al[2][4], Bh[4][4], Bl[4][4];
            #pragma unroll
            for (int mf = 0; mf < 2; mf++) {
                int code = mf*16 + (lane & 15);
                uint32_t pc = (uint32_t)(ch2*4 + ks*2 + (lane >> 4));
                uint32_t ab = (uint32_t)(code*512) + ((pc ^ (uint32_t)(code & 7)) << 4);
                ldsm4(sbase + K2_ASG + ab, Ah[mf]);
                ldsm4(sbase + K2_ASG + 16384 + ab, Al[mf]);
            }
            int prow = ks*16 + ((lane >> 3) & 1)*8 + (lane & 7);
            #pragma unroll
            for (int np = 0; np < 4; np++) {
                int ccol = w*64 + np*16 + (lane >> 4)*8;
                uint32_t byte = (uint32_t)(prow * 1024 + ccol * 2);
                uint32_t sw = byte ^ (((uint32_t)prow & 7) << 4);
                ldsm4t(s0 + sw, Bh[np]);
                ldsm4t(s0 + 32768 + sw, Bl[np]);
            }
            #pragma unroll
            for (int mf = 0; mf < 2; mf++)
                #pragma unroll
                for (int nj = 0; nj < 8; nj++) {
                    const uint32_t* BH = &Bh[nj >> 1][(nj & 1) * 2];
                    const uint32_t* BL = &Bl[nj >> 1][(nj & 1) * 2];
                    mma16816(acc2[mf][nj], Ah[mf], BH);
                    mma16816(acc2[mf][nj], Ah[mf], BL);
                    mma16816(acc2[mf][nj], Al[mf], BH);
                }
        }
    }

    #pragma unroll
    for (int mf = 0; mf < 2; mf++)
        #pragma unroll
        for (int nj = 0; nj < 8; nj++)
            #pragma unroll
            for (int r = 0; r < 4; r++) {
                int code = mf*16 + (lane >> 2) + (r >> 1) * 8;
                int c = w*64 + nj*8 + (lane & 3)*2 + (r & 1);
                atomicAdd(&g_aggT[((size_t)b*CC + c)*KCODE + code], acc2[mf][nj][r]);
            }
}

// ---------------- k4a / k4b ----------------
__global__ void k4a_feat(
    const float* __restrict__ cw,
    const float* __restrict__ g1, const float* __restrict__ b1,
    const float* __restrict__ m1, const float* __restrict__ v1,
    float* __restrict__ out_feat)
{
    int b = blockIdx.x;
    int c = threadIdx.x;
    float f = 0.f;
    #pragma unroll
    for (int k = 0; k < KCODE; k++) {
        float a = g_aggT[((size_t)b*CC + c)*KCODE + k] - g_asum[b*KCODE + k] * cw[k*CC + c];
        float s = g1[k] * rsqrtf(v1[k] + EPSF);
        float e = fmaxf(fmaf(a - m1[k], s, b1[k]), 0.f);
        f += e;
    }
    f *= (1.f / KCODE);
    g_feat[b*CC + c] = f;
    out_feat[b*CC + c] = f;
}

__global__ void k4b_gamma(const float* __restrict__ fw, const float* __restrict__ fb) {
    __shared__ float fs[CC];
    int b = blockIdx.x;
    int o = threadIdx.x;
    fs[o] = g_feat[b*CC + o];
    __syncthreads();
    float acc = fb[o];
    const float* row = fw + (size_t)o * CC;
    #pragma unroll 8
    for (int c = 0; c < CC; c++) acc = fmaf(fs[c], row[c], acc);
    g_gamma[b*CC + o] = 1.f / (1.f + __expf(-acc));
}

// ---------------- k5: out = relu(x * (1 + gamma)), one (b,c) row per block ----------------
__global__ __launch_bounds__(256) void k5_gate(const float* __restrict__ x, float* __restrict__ out) {
    int bc = blockIdx.x;                     // b*CC + c
    float g = 1.f + g_gamma[bc];
    const float4* xr = reinterpret_cast<const float4*>(x + (size_t)bc * NN);
    float4* orow = reinterpret_cast<float4*>(out + (size_t)bc * NN);
    #pragma unroll
    for (int i = 0; i < 16; i++) {
        int idx = threadIdx.x + 256 * i;     // 4096 float4 per row
        float4 xv = xr[idx];
        float4 o;
        o.x = fmaxf(xv.x * g, 0.f);
        o.y = fmaxf(xv.y * g, 0.f);
        o.z = fmaxf(xv.z * g, 0.f);
        o.w = fmaxf(xv.w * g, 0.f);
        orow[idx] = o;
    }
}

// ---------------- launch ----------------
extern "C" void kernel_launch(void* const* d_in, const int* in_sizes, int n_in,
                              void* d_out, int out_size) {
    const float* x      = (const float*)d_in[0];
    const float* conv_w = (const float*)d_in[1];
    const float* bn2_g  = (const float*)d_in[2];
    const float* bn2_b  = (const float*)d_in[3];
    const float* bn2_m  = (const float*)d_in[4];
    const float* bn2_v  = (const float*)d_in[5];
    const float* cw     = (const float*)d_in[6];
    const float* scale  = (const float*)d_in[7];
    const float* bn1_g  = (const float*)d_in[8];
    const float* bn1_b  = (const float*)d_in[9];
    const float* bn1_m  = (const float*)d_in[10];
    const float* bn1_v  = (const float*)d_in[11];
    const float* fc_w   = (const float*)d_in[12];
    const float* fc_b   = (const float*)d_in[13];
    float* out = (float*)d_out;

    cudaFuncSetAttribute(k1_mma, cudaFuncAttributeMaxDynamicSharedMemorySize, SM_K1);
    cudaFuncSetAttribute(k23_mma, cudaFuncAttributeMaxDynamicSharedMemorySize, SM_K23);

    // k1 is the 3rd launch; ncu (skip 4) profiles k23 — k1 verified via regs/tensor next round if needed.
    kc_w<<<1056, 256>>>(conv_w, cw);
    kc_x<<<dim3(NN / 32, CC / 64, BB), 256>>>(x);
    k1_mma<<<dim3(CC / 64, NN / 256, BB), 256, SM_K1>>>(bn2_g, bn2_b, bn2_m, bn2_v);
    k23_mma<<<dim3(NN / 256, BB), 256, SM_K23>>>(scale);
    k4a_feat<<<BB, CC>>>(cw, bn1_g, bn1_b, bn1_m, bn1_v, out);
    k4b_gamma<<<BB, CC>>>(fc_w, fc_b);
    k5_gate<<<BB * CC, 256>>>(x, out + BB * CC);
}

// round 16
// speedup vs baseline: 1.0315x; 1.0315x over previous
#include <cuda_runtime.h>
#include <cuda_bf16.h>
#include <cstdint>

#define BB 4
#define CC 512
#define HH 128
#define WW 128
#define NN (HH*WW)      // 16384
#define KCODE 32
#define EPSF 1e-5f

// ---------------- device scratch ----------------
__device__ float g_x2[BB*NN];                               // sum_c z^2 per pixel
__device__ float g_asum[BB*KCODE];
__device__ float g_aggT[BB*CC*KCODE];                       // agg transposed [b][c][k]
__device__ float g_feat[BB*CC];
__device__ float g_gamma[BB*CC];
__device__ float g_c2[KCODE];
__device__ __align__(256) __nv_bfloat16 g_whi[CC*CC];       // conv_w split [o][c]
__device__ __align__(256) __nv_bfloat16 g_wlo[CC*CC];
__device__ __align__(256) __nv_bfloat16 g_cwhi[KCODE*CC];   // codewords split [k][c]
__device__ __align__(256) __nv_bfloat16 g_cwlo[KCODE*CC];
__device__ __align__(256) __nv_bfloat16 g_xthi[(size_t)BB*NN*CC]; // x transposed+split [b][n][c]
__device__ __align__(256) __nv_bfloat16 g_xtlo[(size_t)BB*NN*CC];
__device__ __align__(256) __nv_bfloat16 g_znhi[(size_t)BB*NN*CC]; // z split [b][n][c]
__device__ __align__(256) __nv_bfloat16 g_znlo[(size_t)BB*NN*CC];

// ---------------- helpers ----------------
__device__ __forceinline__ uint32_t smem_u32(const void* p) {
    uint32_t a;
    asm("{ .reg .u64 t; cvta.to.shared.u64 t, %1; cvt.u32.u64 %0, t; }" : "=r"(a) : "l"(p));
    return a;
}
#define SW128(off) ((off) ^ (((off) >> 3) & 0x70))
#define CP16(dst, src) asm volatile("cp.async.cg.shared.global [%0], [%1], 16;" \
    :: "r"(dst), "l"(__cvta_generic_to_global(src)) : "memory")
#define CP_COMMIT() asm volatile("cp.async.commit_group;" ::: "memory")
#define CP_WAIT0()  asm volatile("cp.async.wait_group 0;" ::: "memory")
#define CP_WAIT1()  asm volatile("cp.async.wait_group 1;" ::: "memory")

__device__ __forceinline__ void ldsm4(uint32_t addr, uint32_t* r) {
    asm volatile("ldmatrix.sync.aligned.m8n8.x4.shared.b16 {%0,%1,%2,%3}, [%4];"
        : "=r"(r[0]), "=r"(r[1]), "=r"(r[2]), "=r"(r[3]) : "r"(addr));
}
__device__ __forceinline__ void ldsm4t(uint32_t addr, uint32_t* r) {
    asm volatile("ldmatrix.sync.aligned.m8n8.x4.trans.shared.b16 {%0,%1,%2,%3}, [%4];"
        : "=r"(r[0]), "=r"(r[1]), "=r"(r[2]), "=r"(r[3]) : "r"(addr));
}
__device__ __forceinline__ void mma16816(float* c, const uint32_t* a, const uint32_t* b) {
    asm volatile("mma.sync.aligned.m16n8k16.row.col.f32.bf16.bf16.f32 "
        "{%0,%1,%2,%3}, {%4,%5,%6,%7}, {%8,%9}, {%0,%1,%2,%3};"
        : "+f"(c[0]), "+f"(c[1]), "+f"(c[2]), "+f"(c[3])
        : "r"(a[0]), "r"(a[1]), "r"(a[2]), "r"(a[3]), "r"(b[0]), "r"(b[1]));
}

// ---------------- kc_w: split conv_w + codewords + c2 + zero accumulators ----------------
__global__ void kc_w(const float* __restrict__ w, const float* __restrict__ cw) {
    if (blockIdx.x >= 1024) {
        __shared__ float red[256];
        int k = blockIdx.x - 1024, t = threadIdx.x;
        float s = 0.f;
        for (int i = t; i < CC; i += 256) {
            float v = cw[k*CC + i];
            __nv_bfloat16 hi = __float2bfloat16(v);
            __nv_bfloat16 lo = __float2bfloat16(v - __bfloat162float(hi));
            g_cwhi[k*CC + i] = hi; g_cwlo[k*CC + i] = lo;
            s = fmaf(v, v, s);
        }
        red[t] = s;
        __syncthreads();
        for (int st = 128; st > 0; st >>= 1) {
            if (t < st) red[t] += red[t + st];
            __syncthreads();
        }
        if (t == 0) g_c2[k] = red[0];
        return;
    }
    int i = blockIdx.x * blockDim.x + threadIdx.x;
    int stride = 1024 * blockDim.x;
    if (i < CC*CC) {
        float v = w[i];
        __nv_bfloat16 hi = __float2bfloat16(v);
        __nv_bfloat16 lo = __float2bfloat16(v - __bfloat162float(hi));
        g_whi[i] = hi; g_wlo[i] = lo;
    }
    for (int j = i; j < BB*CC*KCODE; j += stride) g_aggT[j] = 0.f;
    for (int j = i; j < BB*NN; j += stride) g_x2[j] = 0.f;
    if (i < BB*KCODE) g_asum[i] = 0.f;
}

// ---------------- kc_x: transpose + split x -> [b][n][c] bf16 hi/lo ----------------
__global__ __launch_bounds__(256) void kc_x(const float* __restrict__ x) {
    __shared__ float tile[64][33];
    int b = blockIdx.z;
    int c0 = blockIdx.y * 64;
    int n0 = blockIdx.x * 32;
    int t = threadIdx.x;
    const float* xb = x + (size_t)b * CC * NN;

    int nn = t & 31, cg = t >> 5;
    #pragma unroll
    for (int i = 0; i < 8; i++) {
        int cc = cg * 8 + i;
        tile[cc][nn] = xb[(size_t)(c0 + cc) * NN + n0 + nn];
    }
    __syncthreads();
    int pc = t & 31, nr = t >> 5;
    #pragma unroll
    for (int i = 0; i < 4; i++) {
        int n = nr + 8 * i;
        float v0 = tile[pc * 2][n], v1 = tile[pc * 2 + 1][n];
        __nv_bfloat16 h0 = __float2bfloat16(v0), h1 = __float2bfloat16(v1);
        __nv_bfloat16 l0 = __float2bfloat16(v0 - __bfloat162float(h0));
        __nv_bfloat16 l1 = __float2bfloat16(v1 - __bfloat162float(h1));
        size_t idx = ((size_t)b * NN + n0 + n) * (CC/2) + (c0/2) + pc;
        reinterpret_cast<__nv_bfloat162*>(g_xthi)[idx] = __nv_bfloat162(h0, h1);
        reinterpret_cast<__nv_bfloat162*>(g_xtlo)[idx] = __nv_bfloat162(l0, l1);
    }
}

// ---------------- k1_mma: conv GEMM (split bf16) + BN2 + ReLU ----------------
// Converged config: 128x256 block, 8 warps (2m x 4n), warp tile 64x64, 256 threads.
static constexpr int K1_STAGE = 98304;
static constexpr int SM_K1 = 2 * K1_STAGE;        // 192KB

__global__ __launch_bounds__(256, 1)
void k1_mma(const float* __restrict__ bg, const float* __restrict__ bb_,
            const float* __restrict__ bm, const float* __restrict__ bv)
{
    extern __shared__ char sm[];
    uint32_t sbase = smem_u32(sm);

    int tid = threadIdx.x;
    int lane = tid & 31, wid = tid >> 5;
    int wm = wid & 1, wn = wid >> 1;
    int m0 = blockIdx.x * 128;
    int n0 = blockIdx.y * 256;
    int b  = blockIdx.z;

    auto load_stage = [&](int ch, int st) {
        uint32_t s0 = sbase + st * K1_STAGE;
        #pragma unroll
        for (int i = 0; i < 4; i++) {
            int idx = tid + 256 * i;
            int row = idx >> 3, cc8 = idx & 7;
            uint32_t dst = s0 + SW128((uint32_t)(row * 128 + cc8 * 16));
            size_t aoff = (size_t)(m0 + row) * CC + ch * 64 + cc8 * 8;
            CP16(dst,          g_whi + aoff);
            CP16(dst + 16384,  g_wlo + aoff);
        }
        #pragma unroll
        for (int i = 0; i < 8; i++) {
            int idx = tid + 256 * i;
            int row = idx >> 3, cc8 = idx & 7;
            uint32_t dst = s0 + 32768 + SW128((uint32_t)(row * 128 + cc8 * 16));
            size_t boff = ((size_t)b * NN + n0 + row) * CC + ch * 64 + cc8 * 8;
            CP16(dst,          g_xthi + boff);
            CP16(dst + 32768,  g_xtlo + boff);
        }
    };

    float acc[4][8][4];
    #pragma unroll
    for (int mi = 0; mi < 4; mi++)
        #pragma unroll
        for (int nj = 0; nj < 8; nj++)
            #pragma unroll
            for (int r = 0; r < 4; r++) acc[mi][nj][r] = 0.f;

    int rowA = lane & 15, chA = lane >> 4;
    int rowB = ((lane >> 4) << 3) + (lane & 7), chB = (lane >> 3) & 1;

    load_stage(0, 0); CP_COMMIT();

    for (int ch = 0; ch < 8; ch++) {
        CP_WAIT0();
        __syncthreads();
        if (ch < 7) { load_stage(ch + 1, (ch + 1) & 1); CP_COMMIT(); }

        uint32_t s0 = sbase + (ch & 1) * K1_STAGE;
        #pragma unroll
        for (int ks = 0; ks < 4; ks++) {
            uint32_t ahi[4][4], alo[4][4], bhi[4][4], blo[4][4];
            #pragma unroll
            for (int mi = 0; mi < 4; mi++) {
                uint32_t off = SW128((uint32_t)((wm*64 + mi*16 + rowA) * 128 + ks*32 + chA*16));
                ldsm4(s0 + off, ahi[mi]);
                ldsm4(s0 + 16384 + off, alo[mi]);
            }
            #pragma unroll
            for (int np = 0; np < 4; np++) {
                uint32_t off = 32768 + SW128((uint32_t)((wn*64 + np*16 + rowB) * 128 + ks*32 + chB*16));
                ldsm4(s0 + off, bhi[np]);
                ldsm4(s0 + 32768 + off, blo[np]);
            }
            #pragma unroll
            for (int mi = 0; mi < 4; mi++)
                #pragma unroll
                for (int nj = 0; nj < 8; nj++) {
                    const uint32_t* bh = &bhi[nj >> 1][(nj & 1) * 2];
                    const uint32_t* bl = &blo[nj >> 1][(nj & 1) * 2];
                    mma16816(acc[mi][nj], ahi[mi], bh);
                    mma16816(acc[mi][nj], ahi[mi], bl);
                    mma16816(acc[mi][nj], alo[mi], bh);
                }
        }
    }
    __syncthreads();

    // ---- Epilogue: BN2+ReLU; stage split bf16 [n 256][o 128]; x2 ----
    __nv_bfloat16* sh_hi = reinterpret_cast<__nv_bfloat16*>(sm);
    __nv_bfloat16* sh_lo = sh_hi + 256 * 136;

    float v2acc[16];
    #pragma unroll
    for (int j = 0; j < 16; j++) v2acc[j] = 0.f;

    #pragma unroll
    for (int mi = 0; mi < 4; mi++) {
        #pragma unroll
        for (int rr = 0; rr < 2; rr++) {
            int o_loc = wm*64 + mi*16 + rr*8 + (lane >> 2);
            int o = m0 + o_loc;
            float sc = bg[o] * rsqrtf(bv[o] + EPSF);
            float sh2 = bb_[o] - bm[o] * sc;
            #pragma unroll
            for (int nj = 0; nj < 8; nj++) {
                float z0 = fmaxf(fmaf(acc[mi][nj][rr*2 + 0], sc, sh2), 0.f);
                float z1 = fmaxf(fmaf(acc[mi][nj][rr*2 + 1], sc, sh2), 0.f);
                v2acc[nj*2 + 0] += z0 * z0;
                v2acc[nj*2 + 1] += z1 * z1;
                __nv_bfloat16 h0 = __float2bfloat16(z0), h1 = __float2bfloat16(z1);
                __nv_bfloat16 l0 = __float2bfloat16(z0 - __bfloat162float(h0));
                __nv_bfloat16 l1 = __float2bfloat16(z1 - __bfloat162float(h1));
                int n_loc = wn*64 + nj*8 + (lane & 3) * 2;
                sh_hi[(n_loc + 0) * 136 + o_loc] = h0;
                sh_hi[(n_loc + 1) * 136 + o_loc] = h1;
                sh_lo[(n_loc + 0) * 136 + o_loc] = l0;
                sh_lo[(n_loc + 1) * 136 + o_loc] = l1;
            }
        }
    }
    #pragma unroll
    for (int j = 0; j < 16; j++) {
        v2acc[j] += __shfl_xor_sync(0xffffffffu, v2acc[j], 4);
        v2acc[j] += __shfl_xor_sync(0xffffffffu, v2acc[j], 8);
        v2acc[j] += __shfl_xor_sync(0xffffffffu, v2acc[j], 16);
    }
    if ((lane >> 2) == 0) {
        #pragma unroll
        for (int j = 0; j < 16; j++) {
            int n_loc = wn*64 + (j >> 1) * 8 + (lane & 3) * 2 + (j & 1);
            atomicAdd(&g_x2[b*NN + n0 + n_loc], v2acc[j]);
        }
    }
    __syncthreads();
    #pragma unroll
    for (int i = 0; i < 16; i++) {
        int idx = tid + 256 * i;
        int row = idx >> 4, c16 = idx & 15;
        uint4 vh = *reinterpret_cast<const uint4*>(sh_hi + row * 136 + c16 * 8);
        uint4 vl = *reinterpret_cast<const uint4*>(sh_lo + row * 136 + c16 * 8);
        size_t di = ((size_t)b*NN + n0 + row) * CC + m0 + c16 * 8;
        *reinterpret_cast<uint4*>(&g_znhi[di]) = vh;
        *reinterpret_cast<uint4*>(&g_znlo[di]) = vl;
    }
}

// ---------------- k23_mma: fused assignment + aggregation ----------------
static constexpr int K2_CW_HI = 0;          // phase1 cw; phase2 z-stage buf 0
static constexpr int K2_CW_LO = 32768;
static constexpr int K2_ZST   = 65536;      // phase1 z double buffer (2 x 64KB)
static constexpr int K2_X2S   = 196608;     // 1KB
static constexpr int K2_ASUM  = 197632;     // 128B
static constexpr int K2_ASG   = 197760;     // assign hi 16KB | lo 16KB
static constexpr int SM_K23   = 230528;

__global__ __launch_bounds__(256, 1)
void k23_mma(const float* __restrict__ scale)
{
    extern __shared__ char sm[];
    uint32_t sbase = smem_u32(sm);
    int tid = threadIdx.x, lane = tid & 31, w = tid >> 5;
    int b = blockIdx.y;
    int n0 = blockIdx.x * 256;
    int q = lane >> 2;

    if (tid < 32) *reinterpret_cast<float*>(sm + K2_ASUM + tid*4) = 0.f;
    const uint4* cwh4 = reinterpret_cast<const uint4*>(g_cwhi);
    const uint4* cwl4 = reinterpret_cast<const uint4*>(g_cwlo);
    #pragma unroll
    for (int i = 0; i < 8; i++) {
        int idx = tid + 256 * i;
        int row = idx >> 6, cb = idx & 63;
        uint32_t off = (uint32_t)(row * 1024 + ((cb * 16) ^ ((row & 7) << 4)));
        *reinterpret_cast<uint4*>(sm + K2_CW_HI + off) = cwh4[row * 64 + cb];
        *reinterpret_cast<uint4*>(sm + K2_CW_LO + off) = cwl4[row * 64 + cb];
    }
    *reinterpret_cast<float*>(sm + K2_X2S + tid*4) = g_x2[b*NN + n0 + tid];

    // Phase-1 z loader: [256 n rows][64 c] hi/lo, 128B rows, SW128.
    auto load_z = [&](int ch, uint32_t base) {
        uint32_t s0 = sbase + base;
        #pragma unroll
        for (int i = 0; i < 8; i++) {
            int idx = tid + 256 * i;
            int row = idx >> 3, col = idx & 7;
            uint32_t dst = s0 + SW128((uint32_t)(row * 128 + col * 16));
            size_t src = ((size_t)b*NN + n0 + row) * CC + ch * 64 + col * 8;
            CP16(dst,         g_znhi + src);
            CP16(dst + 32768, g_znlo + src);
        }
    };
    // Phase-2 z loader: [32 pixel rows][512 c] hi/lo, 1KB rows, row-xor swizzle.
    auto load_z2 = [&](int ch, uint32_t base) {
        uint32_t s0 = sbase + base;
        #pragma unroll
        for (int i = 0; i < 8; i++) {
            int idx = tid + 256 * i;
            int row = idx >> 6, cb = idx & 63;
            uint32_t byte = (uint32_t)(row * 1024 + cb * 16);
            uint32_t sw = byte ^ (((uint32_t)row & 7) << 4);
            size_t src = ((size_t)b*NN + n0 + ch*32 + row) * CC + cb * 8;
            CP16(s0 + sw,         g_znhi + src);
            CP16(s0 + 32768 + sw, g_znlo + src);
        }
    };

    float acc[2][4][4];
    #pragma unroll
    for (int mf = 0; mf < 2; mf++)
        #pragma unroll
        for (int nj = 0; nj < 4; nj++)
            #pragma unroll
            for (int r = 0; r < 4; r++) acc[mf][nj][r] = 0.f;

    load_z(0, K2_ZST);
    CP_COMMIT();

    // ---- Phase 1: xc GEMM ----
    for (int ch = 0; ch < 8; ch++) {
        CP_WAIT0();
        __syncthreads();
        if (ch < 7) { load_z(ch + 1, K2_ZST + ((ch + 1) & 1) * 65536); CP_COMMIT(); }
        uint32_t zs = sbase + K2_ZST + (ch & 1) * 65536;
        #pragma unroll
        for (int ks = 0; ks < 4; ks++) {
            uint32_t ah[2][4], al[2][4], bh[2][4], bl[2][4];
            #pragma unroll
            for (int mf = 0; mf < 2; mf++) {
                int code = mf * 16 + (lane & 15);
                uint32_t off = (uint32_t)(code * 1024 +
                    ((ch*128 + ks*32 + (lane >> 4) * 16) ^ ((code & 7) << 4)));
                ldsm4(sbase + K2_CW_HI + off, ah[mf]);
                ldsm4(sbase + K2_CW_LO + off, al[mf]);
            }
            #pragma unroll
            for (int p = 0; p < 2; p++) {
                int row = w*32 + p*16 + ((lane >> 4) << 3) + (lane & 7);
                uint32_t off = SW128((uint32_t)(row * 128 + ks*32 + ((lane >> 3) & 1) * 16));
                ldsm4(zs + off, bh[p]);
                ldsm4(zs + off + 32768, bl[p]);
            }
            #pragma unroll
            for (int mf = 0; mf < 2; mf++)
                #pragma unroll
                for (int nj = 0; nj < 4; nj++) {
                    const uint32_t* Bh = &bh[nj >> 1][(nj & 1) * 2];
                    const uint32_t* Bl = &bl[nj >> 1][(nj & 1) * 2];
                    mma16816(acc[mf][nj], ah[mf], Bh);
                    mma16816(acc[mf][nj], ah[mf], Bl);
                    mma16816(acc[mf][nj], al[mf], Bh);
                }
        }
    }

    __syncthreads();
    load_z2(0, 0);     CP_COMMIT();
    load_z2(1, 65536); CP_COMMIT();

    // ---- softmax over codes (m axis) ----
    float s4[4], c24[4];
    #pragma unroll
    for (int ci = 0; ci < 4; ci++) {
        s4[ci] = __ldg(&scale[q + 8*ci]);
        c24[ci] = g_c2[q + 8*ci];
    }
    float l[4][8];
    #pragma unroll
    for (int mf = 0; mf < 2; mf++)
        #pragma unroll
        for (int nj = 0; nj < 4; nj++)
            #pragma unroll
            for (int r = 0; r < 4; r++) {
                int ci = mf*2 + (r >> 1);
                int j  = nj*2 + (r & 1);
                int col = nj*8 + (lane & 3)*2 + (r & 1);
                float x2v = *reinterpret_cast<const float*>(sm + K2_X2S + (w*32 + col)*4);
                l[ci][j] = s4[ci] * (x2v - 2.f * acc[mf][nj][r] + c24[ci]);
            }
    float mx[8], sme[8], inv[8];
    #pragma unroll
    for (int j = 0; j < 8; j++) {
        mx[j] = fmaxf(fmaxf(l[0][j], l[1][j]), fmaxf(l[2][j], l[3][j]));
        mx[j] = fmaxf(mx[j], __shfl_xor_sync(0xffffffffu, mx[j], 4));
        mx[j] = fmaxf(mx[j], __shfl_xor_sync(0xffffffffu, mx[j], 8));
        mx[j] = fmaxf(mx[j], __shfl_xor_sync(0xffffffffu, mx[j], 16));
    }
    #pragma unroll
    for (int j = 0; j < 8; j++) {
        sme[j] = 0.f;
        #pragma unroll
        for (int ci = 0; ci < 4; ci++) {
            float e = __expf(l[ci][j] - mx[j]);
            l[ci][j] = e; sme[j] += e;
        }
        sme[j] += __shfl_xor_sync(0xffffffffu, sme[j], 4);
        sme[j] += __shfl_xor_sync(0xffffffffu, sme[j], 8);
        sme[j] += __shfl_xor_sync(0xffffffffu, sme[j], 16);
        inv[j] = 1.f / sme[j];
    }
    float apart[4];
    #pragma unroll
    for (int ci = 0; ci < 4; ci++) apart[ci] = 0.f;
    #pragma unroll
    for (int ci = 0; ci < 4; ci++)
        #pragma unroll
        for (int j = 0; j < 8; j++) {
            float av = l[ci][j] * inv[j];
            apart[ci] += av;
            int code = q + 8*ci;
            int pix = w*32 + (j >> 1)*8 + (lane & 3)*2 + (j & 1);
            __nv_bfloat16 hv = __float2bfloat16(av);
            __nv_bfloat16 lv = __float2bfloat16(av - __bfloat162float(hv));
            uint32_t aoff = (uint32_t)(code*512) +
                ((((uint32_t)pix >> 3) ^ (uint32_t)(code & 7)) << 4) + ((uint32_t)pix & 7) * 2;
            *reinterpret_cast<__nv_bfloat16*>(sm + K2_ASG + aoff) = hv;
            *reinterpret_cast<__nv_bfloat16*>(sm + K2_ASG + 16384 + aoff) = lv;
        }
    #pragma unroll
    for (int ci = 0; ci < 4; ci++) {
        apart[ci] += __shfl_xor_sync(0xffffffffu, apart[ci], 1);
        apart[ci] += __shfl_xor_sync(0xffffffffu, apart[ci], 2);
    }
    if ((lane & 3) == 0) {
        #pragma unroll
        for (int ci = 0; ci < 4; ci++)
            atomicAdd(reinterpret_cast<float*>(sm + K2_ASUM + (q + 8*ci)*4), apart[ci]);
    }
    __syncthreads();
    if (tid < 32)
        atomicAdd(&g_asum[b*KCODE + tid], *reinterpret_cast<float*>(sm + K2_ASUM + tid*4));

    // ---- Phase 2: C[m=codes 32][n=c 64/warp], contraction over 256 pixels ----
    float acc2[2][8][4];
    #pragma unroll
    for (int mf = 0; mf < 2; mf++)
        #pragma unroll
        for (int nj = 0; nj < 8; nj++)
            #pragma unroll
            for (int r = 0; r < 4; r++) acc2[mf][nj][r] = 0.f;

    for (int ch2 = 0; ch2 < 8; ch2++) {
        if (ch2 == 7) { CP_WAIT0(); } else { CP_WAIT1(); }
        __syncthreads();
        if (ch2 < 6) { load_z2(ch2 + 2, ((ch2 + 2) % 3) * 65536); CP_COMMIT(); }
        uint32_t s0 = sbase + (ch2 % 3) * 65536;

        #pragma unroll
        for (int ks = 0; ks < 2; ks++) {
            uint32_t Ah[2][4], Al[2][4], Bh[4][4], Bl[4][4];
            #pragma unroll
            for (int mf = 0; mf < 2; mf++) {
                int code = mf*16 + (lane & 15);
                uint32_t pc = (uint32_t)(ch2*4 + ks*2 + (lane >> 4));
                uint32_t ab = (uint32_t)(code*512) + ((pc ^ (uint32_t)(code & 7)) << 4);
                ldsm4(sbase + K2_ASG + ab, Ah[mf]);
                ldsm4(sbase + K2_ASG + 16384 + ab, Al[mf]);
            }
            int prow = ks*16 + ((lane >> 3) & 1)*8 + (lane & 7);
            #pragma unroll
            for (int np = 0; np < 4; np++) {
                int ccol = w*64 + np*16 + (lane >> 4)*8;
                uint32_t byte = (uint32_t)(prow * 1024 + ccol * 2);
                uint32_t sw = byte ^ (((uint32_t)prow & 7) << 4);
                ldsm4t(s0 + sw, Bh[np]);
                ldsm4t(s0 + 32768 + sw, Bl[np]);
            }
            #pragma unroll
            for (int mf = 0; mf < 2; mf++)
                #pragma unroll
                for (int nj = 0; nj < 8; nj++) {
                    const uint32_t* BH = &Bh[nj >> 1][(nj & 1) * 2];
                    const uint32_t* BL = &Bl[nj >> 1][(nj & 1) * 2];
                    mma16816(acc2[mf][nj], Ah[mf], BH);
                    mma16816(acc2[mf][nj], Ah[mf], BL);
                    mma16816(acc2[mf][nj], Al[mf], BH);
                }
        }
    }

    #pragma unroll
    for (int mf = 0; mf < 2; mf++)
        #pragma unroll
        for (int nj = 0; nj < 8; nj++)
            #pragma unroll
            for (int r = 0; r < 4; r++) {
                int code = mf*16 + (lane >> 2) + (r >> 1) * 8;
                int c = w*64 + nj*8 + (lane & 3)*2 + (r & 1);
                atomicAdd(&g_aggT[((size_t)b*CC + c)*KCODE + code], acc2[mf][nj][r]);
            }
}

// ---------------- k4a / k4b ----------------
__global__ void k4a_feat(
    const float* __restrict__ cw,
    const float* __restrict__ g1, const float* __restrict__ b1,
    const float* __restrict__ m1, const float* __restrict__ v1,
    float* __restrict__ out_feat)
{
    int b = blockIdx.x;
    int c = threadIdx.x;
    float f = 0.f;
    #pragma unroll
    for (int k = 0; k < KCODE; k++) {
        float a = g_aggT[((size_t)b*CC + c)*KCODE + k] - g_asum[b*KCODE + k] * cw[k*CC + c];
        float s = g1[k] * rsqrtf(v1[k] + EPSF);
        float e = fmaxf(fmaf(a - m1[k], s, b1[k]), 0.f);
        f += e;
    }
    f *= (1.f / KCODE);
    g_feat[b*CC + c] = f;
    out_feat[b*CC + c] = f;
}

__global__ void k4b_gamma(const float* __restrict__ fw, const float* __restrict__ fb) {
    __shared__ float fs[CC];
    int b = blockIdx.x;
    int o = threadIdx.x;
    fs[o] = g_feat[b*CC + o];
    __syncthreads();
    float acc = fb[o];
    const float* row = fw + (size_t)o * CC;
    #pragma unroll 8
    for (int c = 0; c < CC; c++) acc = fmaf(fs[c], row[c], acc);
    g_gamma[b*CC + o] = 1.f / (1.f + __expf(-acc));
}

// ---------------- k5: out = relu(x * (1 + gamma)), one (b,c) row per block ----------------
__global__ __launch_bounds__(256) void k5_gate(const float* __restrict__ x, float* __restrict__ out) {
    int bc = blockIdx.x;                     // b*CC + c
    float g = 1.f + g_gamma[bc];
    const float4* xr = reinterpret_cast<const float4*>(x + (size_t)bc * NN);
    float4* orow = reinterpret_cast<float4*>(out + (size_t)bc * NN);
    #pragma unroll
    for (int i = 0; i < 16; i++) {
        int idx = threadIdx.x + 256 * i;     // 4096 float4 per row
        float4 xv = xr[idx];
        float4 o;
        o.x = fmaxf(xv.x * g, 0.f);
        o.y = fmaxf(xv.y * g, 0.f);
        o.z = fmaxf(xv.z * g, 0.f);
        o.w = fmaxf(xv.w * g, 0.f);
        orow[idx] = o;
    }
}

// ---------------- launch ----------------
extern "C" void kernel_launch(void* const* d_in, const int* in_sizes, int n_in,
                              void* d_out, int out_size) {
    const float* x      = (const float*)d_in[0];
    const float* conv_w = (const float*)d_in[1];
    const float* bn2_g  = (const float*)d_in[2];
    const float* bn2_b  = (const float*)d_in[3];
    const float* bn2_m  = (const float*)d_in[4];
    const float* bn2_v  = (const float*)d_in[5];
    const float* cw     = (const float*)d_in[6];
    const float* scale  = (const float*)d_in[7];
    const float* bn1_g  = (const float*)d_in[8];
    const float* bn1_b  = (const float*)d_in[9];
    const float* bn1_m  = (const float*)d_in[10];
    const float* bn1_v  = (const float*)d_in[11];
    const float* fc_w   = (const float*)d_in[12];
    const float* fc_b   = (const float*)d_in[13];
    float* out = (float*)d_out;

    cudaFuncSetAttribute(k1_mma, cudaFuncAttributeMaxDynamicSharedMemorySize, SM_K1);
    cudaFuncSetAttribute(k23_mma, cudaFuncAttributeMaxDynamicSharedMemorySize, SM_K23);

    kc_w<<<1056, 256>>>(conv_w, cw);
    kc_x<<<dim3(NN / 32, CC / 64, BB), 256>>>(x);
    k1_mma<<<dim3(CC / 128, NN / 256, BB), 256, SM_K1>>>(bn2_g, bn2_b, bn2_m, bn2_v);
    k23_mma<<<dim3(NN / 256, BB), 256, SM_K23>>>(scale);
    k4a_feat<<<BB, CC>>>(cw, bn1_g, bn1_b, bn1_m, bn1_v, out);
    k4b_gamma<<<BB, CC>>>(fc_w, fc_b);
    k5_gate<<<BB * CC, 256>>>(x, out + BB * CC);
}

// round 17
// speedup vs baseline: 1.0530x; 1.0209x over previous
#include <cuda_runtime.h>
#include <cuda_bf16.h>
#include <cstdint>

#define BB 4
#define CC 512
#define HH 128
#define WW 128
#define NN (HH*WW)      // 16384
#define KCODE 32
#define EPSF 1e-5f

// ---------------- device scratch ----------------
__device__ float g_x2[BB*NN];                               // sum_c z^2 per pixel
__device__ float g_asum[BB*KCODE];
__device__ float g_aggT[BB*CC*KCODE];                       // agg transposed [b][c][k]
__device__ float g_feat[BB*CC];
__device__ float g_gamma[BB*CC];
__device__ float g_c2[KCODE];
__device__ __align__(256) __nv_bfloat16 g_whi[CC*CC];       // conv_w split [o][c]
__device__ __align__(256) __nv_bfloat16 g_wlo[CC*CC];
__device__ __align__(256) __nv_bfloat16 g_cwhi[KCODE*CC];   // codewords split [k][c]
__device__ __align__(256) __nv_bfloat16 g_cwlo[KCODE*CC];
__device__ __align__(256) __nv_bfloat16 g_xthi[(size_t)BB*NN*CC]; // x transposed+split [b][n][c]
__device__ __align__(256) __nv_bfloat16 g_xtlo[(size_t)BB*NN*CC];
__device__ __align__(256) __nv_bfloat16 g_znhi[(size_t)BB*NN*CC]; // z split [b][n][c]
__device__ __align__(256) __nv_bfloat16 g_znlo[(size_t)BB*NN*CC];

// ---------------- helpers ----------------
__device__ __forceinline__ uint32_t smem_u32(const void* p) {
    uint32_t a;
    asm("{ .reg .u64 t; cvta.to.shared.u64 t, %1; cvt.u32.u64 %0, t; }" : "=r"(a) : "l"(p));
    return a;
}
#define SW128(off) ((off) ^ (((off) >> 3) & 0x70))
#define CP16(dst, src) asm volatile("cp.async.cg.shared.global [%0], [%1], 16;" \
    :: "r"(dst), "l"(__cvta_generic_to_global(src)) : "memory")
#define CP_COMMIT() asm volatile("cp.async.commit_group;" ::: "memory")
#define CP_WAIT0()  asm volatile("cp.async.wait_group 0;" ::: "memory")
#define CP_WAIT1()  asm volatile("cp.async.wait_group 1;" ::: "memory")

__device__ __forceinline__ void ldsm4(uint32_t addr, uint32_t* r) {
    asm volatile("ldmatrix.sync.aligned.m8n8.x4.shared.b16 {%0,%1,%2,%3}, [%4];"
        : "=r"(r[0]), "=r"(r[1]), "=r"(r[2]), "=r"(r[3]) : "r"(addr));
}
__device__ __forceinline__ void ldsm4t(uint32_t addr, uint32_t* r) {
    asm volatile("ldmatrix.sync.aligned.m8n8.x4.trans.shared.b16 {%0,%1,%2,%3}, [%4];"
        : "=r"(r[0]), "=r"(r[1]), "=r"(r[2]), "=r"(r[3]) : "r"(addr));
}
__device__ __forceinline__ void mma16816(float* c, const uint32_t* a, const uint32_t* b) {
    asm volatile("mma.sync.aligned.m16n8k16.row.col.f32.bf16.bf16.f32 "
        "{%0,%1,%2,%3}, {%4,%5,%6,%7}, {%8,%9}, {%0,%1,%2,%3};"
        : "+f"(c[0]), "+f"(c[1]), "+f"(c[2]), "+f"(c[3])
        : "r"(a[0]), "r"(a[1]), "r"(a[2]), "r"(a[3]), "r"(b[0]), "r"(b[1]));
}

// ---------------- kc_w: split conv_w + codewords + c2 + zero accumulators ----------------
__global__ void kc_w(const float* __restrict__ w, const float* __restrict__ cw) {
    if (blockIdx.x >= 1024) {
        __shared__ float red[256];
        int k = blockIdx.x - 1024, t = threadIdx.x;
        float s = 0.f;
        for (int i = t; i < CC; i += 256) {
            float v = cw[k*CC + i];
            __nv_bfloat16 hi = __float2bfloat16(v);
            __nv_bfloat16 lo = __float2bfloat16(v - __bfloat162float(hi));
            g_cwhi[k*CC + i] = hi; g_cwlo[k*CC + i] = lo;
            s = fmaf(v, v, s);
        }
        red[t] = s;
        __syncthreads();
        for (int st = 128; st > 0; st >>= 1) {
            if (t < st) red[t] += red[t + st];
            __syncthreads();
        }
        if (t == 0) g_c2[k] = red[0];
        return;
    }
    int i = blockIdx.x * blockDim.x + threadIdx.x;
    int stride = 1024 * blockDim.x;
    if (i < CC*CC) {
        float v = w[i];
        __nv_bfloat16 hi = __float2bfloat16(v);
        __nv_bfloat16 lo = __float2bfloat16(v - __bfloat162float(hi));
        g_whi[i] = hi; g_wlo[i] = lo;
    }
    for (int j = i; j < BB*CC*KCODE; j += stride) g_aggT[j] = 0.f;
    for (int j = i; j < BB*NN; j += stride) g_x2[j] = 0.f;
    if (i < BB*KCODE) g_asum[i] = 0.f;
}

// ---------------- kc_x: transpose + split x -> [b][n][c] bf16 hi/lo ----------------
// 64c x 64n tile per block, float4 loads (LDG.128), 256 threads.
__global__ __launch_bounds__(256) void kc_x(const float* __restrict__ x) {
    __shared__ float tile[64][65];
    int b = blockIdx.z;
    int c0 = blockIdx.y * 64;
    int n0 = blockIdx.x * 64;
    int t = threadIdx.x;
    const float* xb = x + (size_t)b * CC * NN;

    // load: 64 c-rows x 64 n floats as float4; thread t -> c=(t>>4)+16i, n4=(t&15)*4
    #pragma unroll
    for (int i = 0; i < 4; i++) {
        int cc = (t >> 4) + i * 16;
        int n4 = (t & 15) * 4;
        float4 v = *reinterpret_cast<const float4*>(&xb[(size_t)(c0 + cc) * NN + n0 + n4]);
        tile[cc][n4 + 0] = v.x;
        tile[cc][n4 + 1] = v.y;
        tile[cc][n4 + 2] = v.z;
        tile[cc][n4 + 3] = v.w;
    }
    __syncthreads();
    // store: [n][c] split bf16x2; thread t -> n=(t>>5)+8i, pc=t&31 (c-pair)
    int pc = t & 31;
    #pragma unroll
    for (int i = 0; i < 8; i++) {
        int n = (t >> 5) + 8 * i;
        float v0 = tile[pc * 2][n], v1 = tile[pc * 2 + 1][n];
        __nv_bfloat16 h0 = __float2bfloat16(v0), h1 = __float2bfloat16(v1);
        __nv_bfloat16 l0 = __float2bfloat16(v0 - __bfloat162float(h0));
        __nv_bfloat16 l1 = __float2bfloat16(v1 - __bfloat162float(h1));
        size_t idx = ((size_t)b * NN + n0 + n) * (CC/2) + (c0/2) + pc;
        reinterpret_cast<__nv_bfloat162*>(g_xthi)[idx] = __nv_bfloat162(h0, h1);
        reinterpret_cast<__nv_bfloat162*>(g_xtlo)[idx] = __nv_bfloat162(l0, l1);
    }
}

// ---------------- k1_mma: conv GEMM (split bf16) + BN2 + ReLU ----------------
// Converged config: 128x256 block, 8 warps (2m x 4n), warp tile 64x64, 256 threads.
static constexpr int K1_STAGE = 98304;
static constexpr int SM_K1 = 2 * K1_STAGE;        // 192KB

__global__ __launch_bounds__(256, 1)
void k1_mma(const float* __restrict__ bg, const float* __restrict__ bb_,
            const float* __restrict__ bm, const float* __restrict__ bv)
{
    extern __shared__ char sm[];
    uint32_t sbase = smem_u32(sm);

    int tid = threadIdx.x;
    int lane = tid & 31, wid = tid >> 5;
    int wm = wid & 1, wn = wid >> 1;
    int m0 = blockIdx.x * 128;
    int n0 = blockIdx.y * 256;
    int b  = blockIdx.z;

    auto load_stage = [&](int ch, int st) {
        uint32_t s0 = sbase + st * K1_STAGE;
        #pragma unroll
        for (int i = 0; i < 4; i++) {
            int idx = tid + 256 * i;
            int row = idx >> 3, cc8 = idx & 7;
            uint32_t dst = s0 + SW128((uint32_t)(row * 128 + cc8 * 16));
            size_t aoff = (size_t)(m0 + row) * CC + ch * 64 + cc8 * 8;
            CP16(dst,          g_whi + aoff);
            CP16(dst + 16384,  g_wlo + aoff);
        }
        #pragma unroll
        for (int i = 0; i < 8; i++) {
            int idx = tid + 256 * i;
            int row = idx >> 3, cc8 = idx & 7;
            uint32_t dst = s0 + 32768 + SW128((uint32_t)(row * 128 + cc8 * 16));
            size_t boff = ((size_t)b * NN + n0 + row) * CC + ch * 64 + cc8 * 8;
            CP16(dst,          g_xthi + boff);
            CP16(dst + 32768,  g_xtlo + boff);
        }
    };

    float acc[4][8][4];
    #pragma unroll
    for (int mi = 0; mi < 4; mi++)
        #pragma unroll
        for (int nj = 0; nj < 8; nj++)
            #pragma unroll
            for (int r = 0; r < 4; r++) acc[mi][nj][r] = 0.f;

    int rowA = lane & 15, chA = lane >> 4;
    int rowB = ((lane >> 4) << 3) + (lane & 7), chB = (lane >> 3) & 1;

    load_stage(0, 0); CP_COMMIT();

    for (int ch = 0; ch < 8; ch++) {
        CP_WAIT0();
        __syncthreads();
        if (ch < 7) { load_stage(ch + 1, (ch + 1) & 1); CP_COMMIT(); }

        uint32_t s0 = sbase + (ch & 1) * K1_STAGE;
        #pragma unroll
        for (int ks = 0; ks < 4; ks++) {
            uint32_t ahi[4][4], alo[4][4], bhi[4][4], blo[4][4];
            #pragma unroll
            for (int mi = 0; mi < 4; mi++) {
                uint32_t off = SW128((uint32_t)((wm*64 + mi*16 + rowA) * 128 + ks*32 + chA*16));
                ldsm4(s0 + off, ahi[mi]);
                ldsm4(s0 + 16384 + off, alo[mi]);
            }
            #pragma unroll
            for (int np = 0; np < 4; np++) {
                uint32_t off = 32768 + SW128((uint32_t)((wn*64 + np*16 + rowB) * 128 + ks*32 + chB*16));
                ldsm4(s0 + off, bhi[np]);
                ldsm4(s0 + 32768 + off, blo[np]);
            }
            #pragma unroll
            for (int mi = 0; mi < 4; mi++)
                #pragma unroll
                for (int nj = 0; nj < 8; nj++) {
                    const uint32_t* bh = &bhi[nj >> 1][(nj & 1) * 2];
                    const uint32_t* bl = &blo[nj >> 1][(nj & 1) * 2];
                    mma16816(acc[mi][nj], ahi[mi], bh);
                    mma16816(acc[mi][nj], ahi[mi], bl);
                    mma16816(acc[mi][nj], alo[mi], bh);
                }
        }
    }
    __syncthreads();

    // ---- Epilogue: BN2+ReLU; stage split bf16 [n 256][o 128]; x2 ----
    __nv_bfloat16* sh_hi = reinterpret_cast<__nv_bfloat16*>(sm);
    __nv_bfloat16* sh_lo = sh_hi + 256 * 136;

    float v2acc[16];
    #pragma unroll
    for (int j = 0; j < 16; j++) v2acc[j] = 0.f;

    #pragma unroll
    for (int mi = 0; mi < 4; mi++) {
        #pragma unroll
        for (int rr = 0; rr < 2; rr++) {
            int o_loc = wm*64 + mi*16 + rr*8 + (lane >> 2);
            int o = m0 + o_loc;
            float sc = bg[o] * rsqrtf(bv[o] + EPSF);
            float sh2 = bb_[o] - bm[o] * sc;
            #pragma unroll
            for (int nj = 0; nj < 8; nj++) {
                float z0 = fmaxf(fmaf(acc[mi][nj][rr*2 + 0], sc, sh2), 0.f);
                float z1 = fmaxf(fmaf(acc[mi][nj][rr*2 + 1], sc, sh2), 0.f);
                v2acc[nj*2 + 0] += z0 * z0;
                v2acc[nj*2 + 1] += z1 * z1;
                __nv_bfloat16 h0 = __float2bfloat16(z0), h1 = __float2bfloat16(z1);
                __nv_bfloat16 l0 = __float2bfloat16(z0 - __bfloat162float(h0));
                __nv_bfloat16 l1 = __float2bfloat16(z1 - __bfloat162float(h1));
                int n_loc = wn*64 + nj*8 + (lane & 3) * 2;
                sh_hi[(n_loc + 0) * 136 + o_loc] = h0;
                sh_hi[(n_loc + 1) * 136 + o_loc] = h1;
                sh_lo[(n_loc + 0) * 136 + o_loc] = l0;
                sh_lo[(n_loc + 1) * 136 + o_loc] = l1;
            }
        }
    }
    #pragma unroll
    for (int j = 0; j < 16; j++) {
        v2acc[j] += __shfl_xor_sync(0xffffffffu, v2acc[j], 4);
        v2acc[j] += __shfl_xor_sync(0xffffffffu, v2acc[j], 8);
        v2acc[j] += __shfl_xor_sync(0xffffffffu, v2acc[j], 16);
    }
    if ((lane >> 2) == 0) {
        #pragma unroll
        for (int j = 0; j < 16; j++) {
            int n_loc = wn*64 + (j >> 1) * 8 + (lane & 3) * 2 + (j & 1);
            atomicAdd(&g_x2[b*NN + n0 + n_loc], v2acc[j]);
        }
    }
    __syncthreads();
    #pragma unroll
    for (int i = 0; i < 16; i++) {
        int idx = tid + 256 * i;
        int row = idx >> 4, c16 = idx & 15;
        uint4 vh = *reinterpret_cast<const uint4*>(sh_hi + row * 136 + c16 * 8);
        uint4 vl = *reinterpret_cast<const uint4*>(sh_lo + row * 136 + c16 * 8);
        size_t di = ((size_t)b*NN + n0 + row) * CC + m0 + c16 * 8;
        *reinterpret_cast<uint4*>(&g_znhi[di]) = vh;
        *reinterpret_cast<uint4*>(&g_znlo[di]) = vl;
    }
}

// ---------------- k23_mma: fused assignment + aggregation ----------------
static constexpr int K2_CW_HI = 0;          // phase1 cw; phase2 z-stage buf 0
static constexpr int K2_CW_LO = 32768;
static constexpr int K2_ZST   = 65536;      // phase1 z double buffer (2 x 64KB)
static constexpr int K2_X2S   = 196608;     // 1KB
static constexpr int K2_ASUM  = 197632;     // 128B
static constexpr int K2_ASG   = 197760;     // assign hi 16KB | lo 16KB
static constexpr int SM_K23   = 230528;

__global__ __launch_bounds__(256, 1)
void k23_mma(const float* __restrict__ scale)
{
    extern __shared__ char sm[];
    uint32_t sbase = smem_u32(sm);
    int tid = threadIdx.x, lane = tid & 31, w = tid >> 5;
    int b = blockIdx.y;
    int n0 = blockIdx.x * 256;
    int q = lane >> 2;

    if (tid < 32) *reinterpret_cast<float*>(sm + K2_ASUM + tid*4) = 0.f;
    const uint4* cwh4 = reinterpret_cast<const uint4*>(g_cwhi);
    const uint4* cwl4 = reinterpret_cast<const uint4*>(g_cwlo);
    #pragma unroll
    for (int i = 0; i < 8; i++) {
        int idx = tid + 256 * i;
        int row = idx >> 6, cb = idx & 63;
        uint32_t off = (uint32_t)(row * 1024 + ((cb * 16) ^ ((row & 7) << 4)));
        *reinterpret_cast<uint4*>(sm + K2_CW_HI + off) = cwh4[row * 64 + cb];
        *reinterpret_cast<uint4*>(sm + K2_CW_LO + off) = cwl4[row * 64 + cb];
    }
    *reinterpret_cast<float*>(sm + K2_X2S + tid*4) = g_x2[b*NN + n0 + tid];

    // Phase-1 z loader: [256 n rows][64 c] hi/lo, 128B rows, SW128.
    auto load_z = [&](int ch, uint32_t base) {
        uint32_t s0 = sbase + base;
        #pragma unroll
        for (int i = 0; i < 8; i++) {
            int idx = tid + 256 * i;
            int row = idx >> 3, col = idx & 7;
            uint32_t dst = s0 + SW128((uint32_t)(row * 128 + col * 16));
            size_t src = ((size_t)b*NN + n0 + row) * CC + ch * 64 + col * 8;
            CP16(dst,         g_znhi + src);
            CP16(dst + 32768, g_znlo + src);
        }
    };
    // Phase-2 z loader: [32 pixel rows][512 c] hi/lo, 1KB rows, row-xor swizzle.
    auto load_z2 = [&](int ch, uint32_t base) {
        uint32_t s0 = sbase + base;
        #pragma unroll
        for (int i = 0; i < 8; i++) {
            int idx = tid + 256 * i;
            int row = idx >> 6, cb = idx & 63;
            uint32_t byte = (uint32_t)(row * 1024 + cb * 16);
            uint32_t sw = byte ^ (((uint32_t)row & 7) << 4);
            size_t src = ((size_t)b*NN + n0 + ch*32 + row) * CC + cb * 8;
            CP16(s0 + sw,         g_znhi + src);
            CP16(s0 + 32768 + sw, g_znlo + src);
        }
    };

    float acc[2][4][4];
    #pragma unroll
    for (int mf = 0; mf < 2; mf++)
        #pragma unroll
        for (int nj = 0; nj < 4; nj++)
            #pragma unroll
            for (int r = 0; r < 4; r++) acc[mf][nj][r] = 0.f;

    load_z(0, K2_ZST);
    CP_COMMIT();

    // ---- Phase 1: xc GEMM ----
    for (int ch = 0; ch < 8; ch++) {
        CP_WAIT0();
        __syncthreads();
        if (ch < 7) { load_z(ch + 1, K2_ZST + ((ch + 1) & 1) * 65536); CP_COMMIT(); }
        uint32_t zs = sbase + K2_ZST + (ch & 1) * 65536;
        #pragma unroll
        for (int ks = 0; ks < 4; ks++) {
            uint32_t ah[2][4], al[2][4], bh[2][4], bl[2][4];
            #pragma unroll
            for (int mf = 0; mf < 2; mf++) {
                int code = mf * 16 + (lane & 15);
                uint32_t off = (uint32_t)(code * 1024 +
                    ((ch*128 + ks*32 + (lane >> 4) * 16) ^ ((code & 7) << 4)));
                ldsm4(sbase + K2_CW_HI + off, ah[mf]);
                ldsm4(sbase + K2_CW_LO + off, al[mf]);
            }
            #pragma unroll
            for (int p = 0; p < 2; p++) {
                int row = w*32 + p*16 + ((lane >> 4) << 3) + (lane & 7);
                uint32_t off = SW128((uint32_t)(row * 128 + ks*32 + ((lane >> 3) & 1) * 16));
                ldsm4(zs + off, bh[p]);
                ldsm4(zs + off + 32768, bl[p]);
            }
            #pragma unroll
            for (int mf = 0; mf < 2; mf++)
                #pragma unroll
                for (int nj = 0; nj < 4; nj++) {
                    const uint32_t* Bh = &bh[nj >> 1][(nj & 1) * 2];
                    const uint32_t* Bl = &bl[nj >> 1][(nj & 1) * 2];
                    mma16816(acc[mf][nj], ah[mf], Bh);
                    mma16816(acc[mf][nj], ah[mf], Bl);
                    mma16816(acc[mf][nj], al[mf], Bh);
                }
        }
    }

    __syncthreads();
    load_z2(0, 0);     CP_COMMIT();
    load_z2(1, 65536); CP_COMMIT();

    // ---- softmax over codes (m axis) ----
    float s4[4], c24[4];
    #pragma unroll
    for (int ci = 0; ci < 4; ci++) {
        s4[ci] = __ldg(&scale[q + 8*ci]);
        c24[ci] = g_c2[q + 8*ci];
    }
    float l[4][8];
    #pragma unroll
    for (int mf = 0; mf < 2; mf++)
        #pragma unroll
        for (int nj = 0; nj < 4; nj++)
            #pragma unroll
            for (int r = 0; r < 4; r++) {
                int ci = mf*2 + (r >> 1);
                int j  = nj*2 + (r & 1);
                int col = nj*8 + (lane & 3)*2 + (r & 1);
                float x2v = *reinterpret_cast<const float*>(sm + K2_X2S + (w*32 + col)*4);
                l[ci][j] = s4[ci] * (x2v - 2.f * acc[mf][nj][r] + c24[ci]);
            }
    float mx[8], sme[8], inv[8];
    #pragma unroll
    for (int j = 0; j < 8; j++) {
        mx[j] = fmaxf(fmaxf(l[0][j], l[1][j]), fmaxf(l[2][j], l[3][j]));
        mx[j] = fmaxf(mx[j], __shfl_xor_sync(0xffffffffu, mx[j], 4));
        mx[j] = fmaxf(mx[j], __shfl_xor_sync(0xffffffffu, mx[j], 8));
        mx[j] = fmaxf(mx[j], __shfl_xor_sync(0xffffffffu, mx[j], 16));
    }
    #pragma unroll
    for (int j = 0; j < 8; j++) {
        sme[j] = 0.f;
        #pragma unroll
        for (int ci = 0; ci < 4; ci++) {
            float e = __expf(l[ci][j] - mx[j]);
            l[ci][j] = e; sme[j] += e;
        }
        sme[j] += __shfl_xor_sync(0xffffffffu, sme[j], 4);
        sme[j] += __shfl_xor_sync(0xffffffffu, sme[j], 8);
        sme[j] += __shfl_xor_sync(0xffffffffu, sme[j], 16);
        inv[j] = 1.f / sme[j];
    }
    float apart[4];
    #pragma unroll
    for (int ci = 0; ci < 4; ci++) apart[ci] = 0.f;
    #pragma unroll
    for (int ci = 0; ci < 4; ci++)
        #pragma unroll
        for (int j = 0; j < 8; j++) {
            float av = l[ci][j] * inv[j];
            apart[ci] += av;
            int code = q + 8*ci;
            int pix = w*32 + (j >> 1)*8 + (lane & 3)*2 + (j & 1);
            __nv_bfloat16 hv = __float2bfloat16(av);
            __nv_bfloat16 lv = __float2bfloat16(av - __bfloat162float(hv));
            uint32_t aoff = (uint32_t)(code*512) +
                ((((uint32_t)pix >> 3) ^ (uint32_t)(code & 7)) << 4) + ((uint32_t)pix & 7) * 2;
            *reinterpret_cast<__nv_bfloat16*>(sm + K2_ASG + aoff) = hv;
            *reinterpret_cast<__nv_bfloat16*>(sm + K2_ASG + 16384 + aoff) = lv;
        }
    #pragma unroll
    for (int ci = 0; ci < 4; ci++) {
        apart[ci] += __shfl_xor_sync(0xffffffffu, apart[ci], 1);
        apart[ci] += __shfl_xor_sync(0xffffffffu, apart[ci], 2);
    }
    if ((lane & 3) == 0) {
        #pragma unroll
        for (int ci = 0; ci < 4; ci++)
            atomicAdd(reinterpret_cast<float*>(sm + K2_ASUM + (q + 8*ci)*4), apart[ci]);
    }
    __syncthreads();
    if (tid < 32)
        atomicAdd(&g_asum[b*KCODE + tid], *reinterpret_cast<float*>(sm + K2_ASUM + tid*4));

    // ---- Phase 2: C[m=codes 32][n=c 64/warp], contraction over 256 pixels ----
    float acc2[2][8][4];
    #pragma unroll
    for (int mf = 0; mf < 2; mf++)
        #pragma unroll
        for (int nj = 0; nj < 8; nj++)
            #pragma unroll
            for (int r = 0; r < 4; r++) acc2[mf][nj][r] = 0.f;

    for (int ch2 = 0; ch2 < 8; ch2++) {
        if (ch2 == 7) { CP_WAIT0(); } else { CP_WAIT1(); }
        __syncthreads();
        if (ch2 < 6) { load_z2(ch2 + 2, ((ch2 + 2) % 3) * 65536); CP_COMMIT(); }
        uint32_t s0 = sbase + (ch2 % 3) * 65536;

        #pragma unroll
        for (int ks = 0; ks < 2; ks++) {
            uint32_t Ah[2][4], Al[2][4], Bh[4][4], Bl[4][4];
            #pragma unroll
            for (int mf = 0; mf < 2; mf++) {
                int code = mf*16 + (lane & 15);
                uint32_t pc = (uint32_t)(ch2*4 + ks*2 + (lane >> 4));
                uint32_t ab = (uint32_t)(code*512) + ((pc ^ (uint32_t)(code & 7)) << 4);
                ldsm4(sbase + K2_ASG + ab, Ah[mf]);
                ldsm4(sbase + K2_ASG + 16384 + ab, Al[mf]);
            }
            int prow = ks*16 + ((lane >> 3) & 1)*8 + (lane & 7);
            #pragma unroll
            for (int np = 0; np < 4; np++) {
                int ccol = w*64 + np*16 + (lane >> 4)*8;
                uint32_t byte = (uint32_t)(prow * 1024 + ccol * 2);
                uint32_t sw = byte ^ (((uint32_t)prow & 7) << 4);
                ldsm4t(s0 + sw, Bh[np]);
                ldsm4t(s0 + 32768 + sw, Bl[np]);
            }
            #pragma unroll
            for (int mf = 0; mf < 2; mf++)
                #pragma unroll
                for (int nj = 0; nj < 8; nj++) {
                    const uint32_t* BH = &Bh[nj >> 1][(nj & 1) * 2];
                    const uint32_t* BL = &Bl[nj >> 1][(nj & 1) * 2];
                    mma16816(acc2[mf][nj], Ah[mf], BH);
                    mma16816(acc2[mf][nj], Ah[mf], BL);
                    mma16816(acc2[mf][nj], Al[mf], BH);
                }
        }
    }

    #pragma unroll
    for (int mf = 0; mf < 2; mf++)
        #pragma unroll
        for (int nj = 0; nj < 8; nj++)
            #pragma unroll
            for (int r = 0; r < 4; r++) {
                int code = mf*16 + (lane >> 2) + (r >> 1) * 8;
                int c = w*64 + nj*8 + (lane & 3)*2 + (r & 1);
                atomicAdd(&g_aggT[((size_t)b*CC + c)*KCODE + code], acc2[mf][nj][r]);
            }
}

// ---------------- k4a / k4b ----------------
__global__ void k4a_feat(
    const float* __restrict__ cw,
    const float* __restrict__ g1, const float* __restrict__ b1,
    const float* __restrict__ m1, const float* __restrict__ v1,
    float* __restrict__ out_feat)
{
    int b = blockIdx.x;
    int c = threadIdx.x;
    float f = 0.f;
    #pragma unroll
    for (int k = 0; k < KCODE; k++) {
        float a = g_aggT[((size_t)b*CC + c)*KCODE + k] - g_asum[b*KCODE + k] * cw[k*CC + c];
        float s = g1[k] * rsqrtf(v1[k] + EPSF);
        float e = fmaxf(fmaf(a - m1[k], s, b1[k]), 0.f);
        f += e;
    }
    f *= (1.f / KCODE);
    g_feat[b*CC + c] = f;
    out_feat[b*CC + c] = f;
}

__global__ void k4b_gamma(const float* __restrict__ fw, const float* __restrict__ fb) {
    __shared__ float fs[CC];
    int b = blockIdx.x;
    int o = threadIdx.x;
    fs[o] = g_feat[b*CC + o];
    __syncthreads();
    float acc = fb[o];
    const float* row = fw + (size_t)o * CC;
    #pragma unroll 8
    for (int c = 0; c < CC; c++) acc = fmaf(fs[c], row[c], acc);
    g_gamma[b*CC + o] = 1.f / (1.f + __expf(-acc));
}

// ---------------- k5: out = relu(x * (1 + gamma)), one (b,c) row per block ----------------
__global__ __launch_bounds__(256) void k5_gate(const float* __restrict__ x, float* __restrict__ out) {
    int bc = blockIdx.x;                     // b*CC + c
    float g = 1.f + g_gamma[bc];
    const float4* xr = reinterpret_cast<const float4*>(x + (size_t)bc * NN);
    float4* orow = reinterpret_cast<float4*>(out + (size_t)bc * NN);
    #pragma unroll
    for (int i = 0; i < 16; i++) {
        int idx = threadIdx.x + 256 * i;     // 4096 float4 per row
        float4 xv = xr[idx];
        float4 o;
        o.x = fmaxf(xv.x * g, 0.f);
        o.y = fmaxf(xv.y * g, 0.f);
        o.z = fmaxf(xv.z * g, 0.f);
        o.w = fmaxf(xv.w * g, 0.f);
        orow[idx] = o;
    }
}

// ---------------- launch ----------------
extern "C" void kernel_launch(void* const* d_in, const int* in_sizes, int n_in,
                              void* d_out, int out_size) {
    const float* x      = (const float*)d_in[0];
    const float* conv_w = (const float*)d_in[1];
    const float* bn2_g  = (const float*)d_in[2];
    const float* bn2_b  = (const float*)d_in[3];
    const float* bn2_m  = (const float*)d_in[4];
    const float* bn2_v  = (const float*)d_in[5];
    const float* cw     = (const float*)d_in[6];
    const float* scale  = (const float*)d_in[7];
    const float* bn1_g  = (const float*)d_in[8];
    const float* bn1_b  = (const float*)d_in[9];
    const float* bn1_m  = (const float*)d_in[10];
    const float* bn1_v  = (const float*)d_in[11];
    const float* fc_w   = (const float*)d_in[12];
    const float* fc_b   = (const float*)d_in[13];
    float* out = (float*)d_out;

    cudaFuncSetAttribute(k1_mma, cudaFuncAttributeMaxDynamicSharedMemorySize, SM_K1);
    cudaFuncSetAttribute(k23_mma, cudaFuncAttributeMaxDynamicSharedMemorySize, SM_K23);

    kc_w<<<1056, 256>>>(conv_w, cw);
    kc_x<<<dim3(NN / 64, CC / 64, BB), 256>>>(x);
    k1_mma<<<dim3(CC / 128, NN / 256, BB), 256, SM_K1>>>(bn2_g, bn2_b, bn2_m, bn2_v);
    k23_mma<<<dim3(NN / 256, BB), 256, SM_K23>>>(scale);
    k4a_feat<<<BB, CC>>>(cw, bn1_g, bn1_b, bn1_m, bn1_v, out);
    k4b_gamma<<<BB, CC>>>(fc_w, fc_b);
    k5_gate<<<BB * CC, 256>>>(x, out + BB * CC);
}